// round 1
// baseline (speedup 1.0000x reference)
#include <cuda_runtime.h>
#include <math.h>

#define D_MODEL 1024
#define N_EXP   8
#define N_TOK   4096
#define FFN_H   2048
#define CAP     N_TOK

// ---------------- scratch (device globals; no allocation allowed) ----------
__device__ int   g_cnt[N_EXP];
__device__ int   g_tok[N_EXP * CAP];
__device__ int   g_slot[N_EXP * CAP];
__device__ float g_wt[N_EXP * CAP];
__device__ float g_probs[N_TOK * N_EXP];
__device__ float g_psum[N_EXP];
__device__ float g_h[(size_t)2 * N_TOK * FFN_H];   // 64 MB: hidden activations per slot

// ---------------- init: zero main output + counters ------------------------
__global__ void zero_kernel(float4* out4, int n4) {
    int i = blockIdx.x * blockDim.x + threadIdx.x;
    if (i < n4) out4[i] = make_float4(0.f, 0.f, 0.f, 0.f);
    if (i < N_EXP) g_cnt[i] = 0;
}

// ---------------- router: logits, softmax, top-2, dispatch lists -----------
__global__ __launch_bounds__(256) void router_kernel(const float* __restrict__ x,
                                                     const float* __restrict__ rw) {
    const int n   = blockIdx.x;
    const int tid = threadIdx.x;

    float part[N_EXP];
#pragma unroll
    for (int e = 0; e < N_EXP; e++) part[e] = 0.f;

    const float* xr = x + (size_t)n * D_MODEL;
    for (int d = tid; d < D_MODEL; d += 256) {
        float xv = xr[d];
#pragma unroll
        for (int e = 0; e < N_EXP; e++) part[e] += xv * rw[e * D_MODEL + d];
    }

    __shared__ float red[N_EXP][256];
#pragma unroll
    for (int e = 0; e < N_EXP; e++) red[e][tid] = part[e];
    __syncthreads();
    for (int s = 128; s > 0; s >>= 1) {
        if (tid < s) {
#pragma unroll
            for (int e = 0; e < N_EXP; e++) red[e][tid] += red[e][tid + s];
        }
        __syncthreads();
    }

    if (tid == 0) {
        float logit[N_EXP];
#pragma unroll
        for (int e = 0; e < N_EXP; e++) logit[e] = red[e][0];

        float m = logit[0];
#pragma unroll
        for (int e = 1; e < N_EXP; e++) m = fmaxf(m, logit[e]);
        float p[N_EXP], s = 0.f;
#pragma unroll
        for (int e = 0; e < N_EXP; e++) { p[e] = expf(logit[e] - m); s += p[e]; }
        float inv = 1.f / s;
#pragma unroll
        for (int e = 0; e < N_EXP; e++) { p[e] *= inv; g_probs[n * N_EXP + e] = p[e]; }

        // top-2 by logits (same ordering as probs; strict > keeps first index on ties)
        int i1 = 0;
#pragma unroll
        for (int e = 1; e < N_EXP; e++) if (logit[e] > logit[i1]) i1 = e;
        int i2 = (i1 == 0) ? 1 : 0;
#pragma unroll
        for (int e = 0; e < N_EXP; e++) if (e != i1 && logit[e] > logit[i2]) i2 = e;

        float denom = p[i1] + p[i2];
        float wA = p[i1] / denom;
        float wB = p[i2] / denom;

        int pos1 = atomicAdd(&g_cnt[i1], 1);
        g_tok[i1 * CAP + pos1]  = n;
        g_slot[i1 * CAP + pos1] = 2 * n;
        g_wt[i1 * CAP + pos1]   = wA;
        int pos2 = atomicAdd(&g_cnt[i2], 1);
        g_tok[i2 * CAP + pos2]  = n;
        g_slot[i2 * CAP + pos2] = 2 * n + 1;
        g_wt[i2 * CAP + pos2]   = wB;
    }
}

// ---------------- deterministic prob-sum per expert ------------------------
__global__ __launch_bounds__(256) void psum_kernel() {
    const int e   = blockIdx.x;
    const int tid = threadIdx.x;
    float s = 0.f;
    for (int n = tid; n < N_TOK; n += 256) s += g_probs[n * N_EXP + e];
    __shared__ float r[256];
    r[tid] = s;
    __syncthreads();
    for (int st = 128; st > 0; st >>= 1) {
        if (tid < st) r[tid] += r[tid + st];
        __syncthreads();
    }
    if (tid == 0) g_psum[e] = r[0];
}

__global__ void aux_kernel(float* out, int out_size) {
    if (threadIdx.x == 0 && blockIdx.x == 0) {
        float a = 0.f;
#pragma unroll
        for (int e = 0; e < N_EXP; e++) {
            float f = (float)g_cnt[e] / (float)(N_TOK * 2);
            float P = g_psum[e] / (float)N_TOK;
            a += f * P;
        }
        a *= (float)N_EXP;
        if (out_size > N_TOK * D_MODEL) out[N_TOK * D_MODEL] = a;
    }
}

// ---------------- grouped GEMM tiles ---------------------------------------
#define BM 64
#define BN 64
#define BK 32
#define APAD 4

// h[slot] = silu(x[tok] @ w1[e]^T + b1[e])
__global__ __launch_bounds__(256) void gemm1_kernel(const float* __restrict__ x,
                                                    const float* __restrict__ w1,
                                                    const float* __restrict__ b1) {
    const int e    = blockIdx.z;
    const int cnt  = g_cnt[e];
    const int row0 = blockIdx.y * BM;
    if (row0 >= cnt) return;
    const int col0 = blockIdx.x * BN;

    __shared__ __align__(16) float As[BK][BM + APAD];
    __shared__ __align__(16) float Bs[BK][BN + APAD];
    __shared__ int toks[BM];
    __shared__ int slots[BM];

    const int tid = threadIdx.x;
    if (tid < BM) {
        int r = row0 + tid;
        if (r < cnt) { toks[tid] = g_tok[e * CAP + r]; slots[tid] = g_slot[e * CAP + r]; }
        else         { toks[tid] = 0;                  slots[tid] = -1; }
    }
    __syncthreads();

    float acc[4][4];
#pragma unroll
    for (int i = 0; i < 4; i++)
#pragma unroll
        for (int j = 0; j < 4; j++) acc[i][j] = 0.f;

    const int tx = tid & 15, ty = tid >> 4;
    const float* wb = w1 + ((size_t)e * FFN_H + col0) * D_MODEL;

    for (int k0 = 0; k0 < D_MODEL; k0 += BK) {
#pragma unroll
        for (int i = 0; i < 2; i++) {
            int lin = tid + i * 256;       // 0..511
            int row = lin >> 3;
            int c4  = (lin & 7) << 2;
            float4 va = *(const float4*)(x + (size_t)toks[row] * D_MODEL + k0 + c4);
            As[c4 + 0][row] = va.x; As[c4 + 1][row] = va.y;
            As[c4 + 2][row] = va.z; As[c4 + 3][row] = va.w;
            float4 vb = *(const float4*)(wb + (size_t)row * D_MODEL + k0 + c4);
            Bs[c4 + 0][row] = vb.x; Bs[c4 + 1][row] = vb.y;
            Bs[c4 + 2][row] = vb.z; Bs[c4 + 3][row] = vb.w;
        }
        __syncthreads();
#pragma unroll
        for (int kk = 0; kk < BK; kk++) {
            float4 a = *(const float4*)&As[kk][ty * 4];
            float4 b = *(const float4*)&Bs[kk][tx * 4];
            float av[4] = {a.x, a.y, a.z, a.w};
            float bv[4] = {b.x, b.y, b.z, b.w};
#pragma unroll
            for (int i = 0; i < 4; i++)
#pragma unroll
                for (int j = 0; j < 4; j++)
                    acc[i][j] = fmaf(av[i], bv[j], acc[i][j]);
        }
        __syncthreads();
    }

#pragma unroll
    for (int i = 0; i < 4; i++) {
        int r = ty * 4 + i;
        int slot = slots[r];
        if (slot >= 0) {
            float* hp = g_h + (size_t)slot * FFN_H + col0 + tx * 4;
#pragma unroll
            for (int j = 0; j < 4; j++) {
                float v = acc[i][j] + b1[e * FFN_H + col0 + tx * 4 + j];
                hp[j] = v / (1.f + expf(-v));   // silu
            }
        }
    }
}

// out[tok] += wt * (h[slot] @ w2[e]^T + b2[e])
__global__ __launch_bounds__(256) void gemm2_kernel(const float* __restrict__ w2,
                                                    const float* __restrict__ b2,
                                                    float* __restrict__ out) {
    const int e    = blockIdx.z;
    const int cnt  = g_cnt[e];
    const int row0 = blockIdx.y * BM;
    if (row0 >= cnt) return;
    const int col0 = blockIdx.x * BN;

    __shared__ __align__(16) float As[BK][BM + APAD];
    __shared__ __align__(16) float Bs[BK][BN + APAD];
    __shared__ int   toks[BM];
    __shared__ int   slots[BM];
    __shared__ float wts[BM];

    const int tid = threadIdx.x;
    if (tid < BM) {
        int r = row0 + tid;
        if (r < cnt) { toks[tid] = g_tok[e * CAP + r]; slots[tid] = g_slot[e * CAP + r]; wts[tid] = g_wt[e * CAP + r]; }
        else         { toks[tid] = -1;                 slots[tid] = 0;                   wts[tid] = 0.f; }
    }
    __syncthreads();

    float acc[4][4];
#pragma unroll
    for (int i = 0; i < 4; i++)
#pragma unroll
        for (int j = 0; j < 4; j++) acc[i][j] = 0.f;

    const int tx = tid & 15, ty = tid >> 4;
    const float* wb = w2 + ((size_t)e * D_MODEL + col0) * FFN_H;

    for (int k0 = 0; k0 < FFN_H; k0 += BK) {
#pragma unroll
        for (int i = 0; i < 2; i++) {
            int lin = tid + i * 256;
            int row = lin >> 3;
            int c4  = (lin & 7) << 2;
            float4 va = *(const float4*)(g_h + (size_t)slots[row] * FFN_H + k0 + c4);
            As[c4 + 0][row] = va.x; As[c4 + 1][row] = va.y;
            As[c4 + 2][row] = va.z; As[c4 + 3][row] = va.w;
            float4 vb = *(const float4*)(wb + (size_t)row * FFN_H + k0 + c4);
            Bs[c4 + 0][row] = vb.x; Bs[c4 + 1][row] = vb.y;
            Bs[c4 + 2][row] = vb.z; Bs[c4 + 3][row] = vb.w;
        }
        __syncthreads();
#pragma unroll
        for (int kk = 0; kk < BK; kk++) {
            float4 a = *(const float4*)&As[kk][ty * 4];
            float4 b = *(const float4*)&Bs[kk][tx * 4];
            float av[4] = {a.x, a.y, a.z, a.w};
            float bv[4] = {b.x, b.y, b.z, b.w};
#pragma unroll
            for (int i = 0; i < 4; i++)
#pragma unroll
                for (int j = 0; j < 4; j++)
                    acc[i][j] = fmaf(av[i], bv[j], acc[i][j]);
        }
        __syncthreads();
    }

#pragma unroll
    for (int i = 0; i < 4; i++) {
        int r = ty * 4 + i;
        int tok = toks[r];
        if (tok >= 0) {
            float wt = wts[r];
#pragma unroll
            for (int j = 0; j < 4; j++) {
                int col = col0 + tx * 4 + j;
                float v = acc[i][j] + b2[e * D_MODEL + col];
                atomicAdd(out + (size_t)tok * D_MODEL + col, wt * v);
            }
        }
    }
}

// ---------------- launch ----------------------------------------------------
extern "C" void kernel_launch(void* const* d_in, const int* in_sizes, int n_in,
                              void* d_out, int out_size) {
    const float* x  = (const float*)d_in[0];
    const float* rw = (const float*)d_in[1];
    const float* w1 = (const float*)d_in[2];
    const float* b1 = (const float*)d_in[3];
    const float* w2 = (const float*)d_in[4];
    const float* b2 = (const float*)d_in[5];
    float* out = (float*)d_out;

    const int n4 = N_TOK * D_MODEL / 4;
    zero_kernel<<<(n4 + 255) / 256, 256>>>((float4*)out, n4);
    router_kernel<<<N_TOK, 256>>>(x, rw);
    psum_kernel<<<N_EXP, 256>>>();
    aux_kernel<<<1, 32>>>(out, out_size);

    dim3 g1(FFN_H / BN, N_TOK / BM, N_EXP);
    gemm1_kernel<<<g1, 256>>>(x, w1, b1);
    dim3 g2(D_MODEL / BN, N_TOK / BM, N_EXP);
    gemm2_kernel<<<g2, 256>>>(w2, b2, out);
}

// round 3
// speedup vs baseline: 2.5118x; 2.5118x over previous
#include <cuda_runtime.h>
#include <cuda_bf16.h>
#include <math.h>
#include <stdint.h>

#define D_MODEL 1024
#define N_EXP   8
#define N_TOK   4096
#define FFN_H   2048
#define CAP     N_TOK

// ---------------- device scratch ----------------
__device__ int   g_cnt[N_EXP];
__device__ int   g_tok[N_EXP * CAP];
__device__ int   g_slot[N_EXP * CAP];
__device__ float g_wt[N_EXP * CAP];
__device__ float g_probs[N_TOK * N_EXP];
__device__ float g_psum[N_EXP];

__device__ __align__(16) __nv_bfloat16 g_x_hi[(size_t)N_TOK * D_MODEL];
__device__ __align__(16) __nv_bfloat16 g_x_lo[(size_t)N_TOK * D_MODEL];
__device__ __align__(16) __nv_bfloat16 g_w1_hi[(size_t)N_EXP * FFN_H * D_MODEL];
__device__ __align__(16) __nv_bfloat16 g_w1_lo[(size_t)N_EXP * FFN_H * D_MODEL];
__device__ __align__(16) __nv_bfloat16 g_w2_hi[(size_t)N_EXP * D_MODEL * FFN_H];
__device__ __align__(16) __nv_bfloat16 g_w2_lo[(size_t)N_EXP * D_MODEL * FFN_H];
__device__ __align__(16) __nv_bfloat16 g_h_hi[(size_t)2 * N_TOK * FFN_H];
__device__ __align__(16) __nv_bfloat16 g_h_lo[(size_t)2 * N_TOK * FFN_H];

// ---------------- portable (compute_103) PTX helpers ----------------
__device__ __forceinline__ uint32_t smem_u32(const void* p) {
    uint32_t a;
    asm("{ .reg .u64 t; cvta.to.shared.u64 t, %1; cvt.u32.u64 %0, t; }" : "=r"(a) : "l"(p));
    return a;
}

#define CP16(dst, src) \
    asm volatile("cp.async.cg.shared.global [%0], [%1], 16;" :: "r"(dst), "l"(src))
#define CP_COMMIT() asm volatile("cp.async.commit_group;" ::: "memory")
#define CP_WAIT0()  asm volatile("cp.async.wait_group 0;" ::: "memory")
#define CP_WAIT1()  asm volatile("cp.async.wait_group 1;" ::: "memory")

#define LDSM4(r, addr) \
    asm volatile("ldmatrix.sync.aligned.m8n8.x4.shared.b16 {%0,%1,%2,%3}, [%4];" \
                 : "=r"((r)[0]), "=r"((r)[1]), "=r"((r)[2]), "=r"((r)[3]) : "r"(addr))
#define LDSM2(r, addr) \
    asm volatile("ldmatrix.sync.aligned.m8n8.x2.shared.b16 {%0,%1}, [%2];" \
                 : "=r"((r)[0]), "=r"((r)[1]) : "r"(addr))

#define MMA16816(c, a, b) \
    asm volatile("mma.sync.aligned.m16n8k16.row.col.f32.bf16.bf16.f32 " \
                 "{%0,%1,%2,%3}, {%4,%5,%6,%7}, {%8,%9}, {%0,%1,%2,%3};" \
                 : "+f"((c)[0]), "+f"((c)[1]), "+f"((c)[2]), "+f"((c)[3]) \
                 : "r"((a)[0]), "r"((a)[1]), "r"((a)[2]), "r"((a)[3]), \
                   "r"((b)[0]), "r"((b)[1]))

__device__ __forceinline__ uint32_t swz(uint32_t off) { return off ^ ((off >> 3) & 0x70); }

// ---------------- tile geometry ----------------
#define BM 128
#define BN 128
#define BKT 64                      // bf16 K elements per stage
#define MAT_BYTES (BM * BKT * 2)    // 16384 per matrix
#define OFF_AH 0
#define OFF_AL 16384
#define OFF_BH 32768
#define OFF_BL 49152
#define STAGE_TOTAL 65536
#define SMEM_DYN (2 * STAGE_TOTAL)

// ---------------- init / router / aux ----------------
__global__ void zero_kernel(float4* out4, int n4) {
    int i = blockIdx.x * blockDim.x + threadIdx.x;
    if (i < n4) out4[i] = make_float4(0.f, 0.f, 0.f, 0.f);
    if (i < N_EXP) g_cnt[i] = 0;
}

__global__ __launch_bounds__(256) void router_kernel(const float* __restrict__ x,
                                                     const float* __restrict__ rw) {
    const int n = blockIdx.x;
    const int tid = threadIdx.x;
    float part[N_EXP];
#pragma unroll
    for (int e = 0; e < N_EXP; e++) part[e] = 0.f;
    const float* xr = x + (size_t)n * D_MODEL;
    for (int d = tid; d < D_MODEL; d += 256) {
        float xv = xr[d];
#pragma unroll
        for (int e = 0; e < N_EXP; e++) part[e] += xv * rw[e * D_MODEL + d];
    }
    __shared__ float red[N_EXP][256];
#pragma unroll
    for (int e = 0; e < N_EXP; e++) red[e][tid] = part[e];
    __syncthreads();
    for (int s = 128; s > 0; s >>= 1) {
        if (tid < s) {
#pragma unroll
            for (int e = 0; e < N_EXP; e++) red[e][tid] += red[e][tid + s];
        }
        __syncthreads();
    }
    if (tid == 0) {
        float logit[N_EXP];
#pragma unroll
        for (int e = 0; e < N_EXP; e++) logit[e] = red[e][0];
        float m = logit[0];
#pragma unroll
        for (int e = 1; e < N_EXP; e++) m = fmaxf(m, logit[e]);
        float p[N_EXP], s = 0.f;
#pragma unroll
        for (int e = 0; e < N_EXP; e++) { p[e] = expf(logit[e] - m); s += p[e]; }
        float inv = 1.f / s;
#pragma unroll
        for (int e = 0; e < N_EXP; e++) { p[e] *= inv; g_probs[n * N_EXP + e] = p[e]; }
        int i1 = 0;
#pragma unroll
        for (int e = 1; e < N_EXP; e++) if (logit[e] > logit[i1]) i1 = e;
        int i2 = (i1 == 0) ? 1 : 0;
#pragma unroll
        for (int e = 0; e < N_EXP; e++) if (e != i1 && logit[e] > logit[i2]) i2 = e;
        float denom = p[i1] + p[i2];
        int pos1 = atomicAdd(&g_cnt[i1], 1);
        g_tok[i1 * CAP + pos1] = n; g_slot[i1 * CAP + pos1] = 2 * n; g_wt[i1 * CAP + pos1] = p[i1] / denom;
        int pos2 = atomicAdd(&g_cnt[i2], 1);
        g_tok[i2 * CAP + pos2] = n; g_slot[i2 * CAP + pos2] = 2 * n + 1; g_wt[i2 * CAP + pos2] = p[i2] / denom;
    }
}

__global__ __launch_bounds__(256) void psum_kernel() {
    const int e = blockIdx.x;
    const int tid = threadIdx.x;
    float s = 0.f;
    for (int n = tid; n < N_TOK; n += 256) s += g_probs[n * N_EXP + e];
    __shared__ float r[256];
    r[tid] = s;
    __syncthreads();
    for (int st = 128; st > 0; st >>= 1) {
        if (tid < st) r[tid] += r[tid + st];
        __syncthreads();
    }
    if (tid == 0) g_psum[e] = r[0];
}

__global__ void aux_kernel(float* out, int out_size) {
    if (threadIdx.x == 0 && blockIdx.x == 0) {
        float a = 0.f;
#pragma unroll
        for (int e = 0; e < N_EXP; e++) {
            float f = (float)g_cnt[e] / (float)(N_TOK * 2);
            float P = g_psum[e] / (float)N_TOK;
            a += f * P;
        }
        a *= (float)N_EXP;
        if (out_size > N_TOK * D_MODEL) out[N_TOK * D_MODEL] = a;
    }
}

// ---------------- fp32 -> bf16 hi/lo split ----------------
__global__ __launch_bounds__(256) void split_kernel(const float4* __restrict__ in,
                                                    __nv_bfloat162* __restrict__ hi2,
                                                    __nv_bfloat162* __restrict__ lo2, int n4) {
    int i = blockIdx.x * blockDim.x + threadIdx.x;
    if (i >= n4) return;
    float4 v = in[i];
    __nv_bfloat16 h0 = __float2bfloat16(v.x), h1 = __float2bfloat16(v.y);
    __nv_bfloat16 h2 = __float2bfloat16(v.z), h3 = __float2bfloat16(v.w);
    __nv_bfloat16 l0 = __float2bfloat16(v.x - __bfloat162float(h0));
    __nv_bfloat16 l1 = __float2bfloat16(v.y - __bfloat162float(h1));
    __nv_bfloat16 l2 = __float2bfloat16(v.z - __bfloat162float(h2));
    __nv_bfloat16 l3 = __float2bfloat16(v.w - __bfloat162float(h3));
    __nv_bfloat162 a, b, c, d;
    a.x = h0; a.y = h1; b.x = h2; b.y = h3;
    c.x = l0; c.y = l1; d.x = l2; d.y = l3;
    hi2[2 * i] = a; hi2[2 * i + 1] = b;
    lo2[2 * i] = c; lo2[2 * i + 1] = d;
}

// ============ grouped GEMM1: h[slot] = silu(x[tok] @ w1[e]^T + b1[e]) ============
__global__ __launch_bounds__(256, 1) void gemm1_mma(const float* __restrict__ b1) {
    const int e = blockIdx.z;
    const int cnt = g_cnt[e];
    const int row0 = blockIdx.y * BM;
    if (row0 >= cnt) return;
    const int col0 = blockIdx.x * BN;

    extern __shared__ char sm[];
    __shared__ int toks[BM];
    __shared__ int slots[BM];

    const int tid = threadIdx.x;
    if (tid < BM) {
        int r = row0 + tid;
        toks[tid]  = (r < cnt) ? g_tok[e * CAP + r]  : 0;
        slots[tid] = (r < cnt) ? g_slot[e * CAP + r] : -1;
    }
    __syncthreads();

    const uint32_t smb = smem_u32(sm);
    const int lr = tid >> 1;              // loader row 0..127
    const int lc0 = (tid & 1) * 4;        // loader first 16B chunk (of 8)

    const size_t a_row_off = (size_t)toks[lr] * D_MODEL;
    const size_t b_row_off = ((size_t)e * FFN_H + col0 + lr) * D_MODEL;

    float acc[4][4][4];
#pragma unroll
    for (int mi = 0; mi < 4; mi++)
#pragma unroll
        for (int ni = 0; ni < 4; ni++)
#pragma unroll
            for (int q = 0; q < 4; q++) acc[mi][ni][q] = 0.f;

    const int lane = tid & 31;
    const int wid = tid >> 5;
    const int wm = wid >> 2;              // 0..1
    const int wn = wid & 3;               // 0..3
    const int arow = lane & 15, ahalf = lane >> 4;
    const int brow = lane & 7,  bhalf = (lane >> 3) & 1;

    const int NT = D_MODEL / BKT;         // 16

    // ---- prologue load stage 0 ----
    {
        const int k0 = 0;
        uint32_t st = smb;
#pragma unroll
        for (int j = 0; j < 4; j++) {
            uint32_t off = (uint32_t)lr * 128 + (lc0 + j) * 16;
            uint32_t so = swz(off);
            CP16(st + OFF_AH + so, (const void*)(g_x_hi + a_row_off + k0 + (lc0 + j) * 8));
            CP16(st + OFF_AL + so, (const void*)(g_x_lo + a_row_off + k0 + (lc0 + j) * 8));
            CP16(st + OFF_BH + so, (const void*)(g_w1_hi + b_row_off + k0 + (lc0 + j) * 8));
            CP16(st + OFF_BL + so, (const void*)(g_w1_lo + b_row_off + k0 + (lc0 + j) * 8));
        }
        CP_COMMIT();
    }

#pragma unroll 1
    for (int it = 0; it < NT; it++) {
        if (it + 1 < NT) {
            const int k0 = (it + 1) * BKT;
            uint32_t st = smb + ((it + 1) & 1) * STAGE_TOTAL;
#pragma unroll
            for (int j = 0; j < 4; j++) {
                uint32_t off = (uint32_t)lr * 128 + (lc0 + j) * 16;
                uint32_t so = swz(off);
                CP16(st + OFF_AH + so, (const void*)(g_x_hi + a_row_off + k0 + (lc0 + j) * 8));
                CP16(st + OFF_AL + so, (const void*)(g_x_lo + a_row_off + k0 + (lc0 + j) * 8));
                CP16(st + OFF_BH + so, (const void*)(g_w1_hi + b_row_off + k0 + (lc0 + j) * 8));
                CP16(st + OFF_BL + so, (const void*)(g_w1_lo + b_row_off + k0 + (lc0 + j) * 8));
            }
            CP_COMMIT();
            CP_WAIT1();
        } else {
            CP_WAIT0();
        }
        __syncthreads();

        const uint32_t sb = smb + (it & 1) * STAGE_TOTAL;
#pragma unroll
        for (int kk = 0; kk < 4; kk++) {
            uint32_t ah[4][4], al[4][4], bh[4][2], bl[4][2];
#pragma unroll
            for (int mi = 0; mi < 4; mi++) {
                uint32_t off = (uint32_t)(wm * 64 + mi * 16 + arow) * 128 + kk * 32 + ahalf * 16;
                uint32_t so = swz(off);
                LDSM4(ah[mi], sb + OFF_AH + so);
                LDSM4(al[mi], sb + OFF_AL + so);
            }
#pragma unroll
            for (int ni = 0; ni < 4; ni++) {
                uint32_t off = (uint32_t)(wn * 32 + ni * 8 + brow) * 128 + kk * 32 + bhalf * 16;
                uint32_t so = swz(off);
                LDSM2(bh[ni], sb + OFF_BH + so);
                LDSM2(bl[ni], sb + OFF_BL + so);
            }
#pragma unroll
            for (int mi = 0; mi < 4; mi++)
#pragma unroll
                for (int ni = 0; ni < 4; ni++) MMA16816(acc[mi][ni], ah[mi], bh[ni]);
#pragma unroll
            for (int mi = 0; mi < 4; mi++)
#pragma unroll
                for (int ni = 0; ni < 4; ni++) MMA16816(acc[mi][ni], ah[mi], bl[ni]);
#pragma unroll
            for (int mi = 0; mi < 4; mi++)
#pragma unroll
                for (int ni = 0; ni < 4; ni++) MMA16816(acc[mi][ni], al[mi], bh[ni]);
        }
        __syncthreads();
    }

    // ---- epilogue: bias + silu + hi/lo bf16 split store ----
    const int gr = lane >> 2, gc2 = (lane & 3) * 2;
    const float* b1e = b1 + (size_t)e * FFN_H;
#pragma unroll
    for (int mi = 0; mi < 4; mi++) {
#pragma unroll
        for (int ni = 0; ni < 4; ni++) {
            int col = col0 + wn * 32 + ni * 8 + gc2;
            float bv0 = b1e[col], bv1 = b1e[col + 1];
#pragma unroll
            for (int half = 0; half < 2; half++) {
                int r = wm * 64 + mi * 16 + gr + half * 8;
                int slot = slots[r];
                if (slot >= 0) {
                    float v0 = acc[mi][ni][half * 2 + 0] + bv0;
                    float v1 = acc[mi][ni][half * 2 + 1] + bv1;
                    float s0 = v0 / (1.f + expf(-v0));
                    float s1 = v1 / (1.f + expf(-v1));
                    __nv_bfloat16 h0 = __float2bfloat16(s0), h1 = __float2bfloat16(s1);
                    __nv_bfloat16 l0 = __float2bfloat16(s0 - __bfloat162float(h0));
                    __nv_bfloat16 l1 = __float2bfloat16(s1 - __bfloat162float(h1));
                    __nv_bfloat162 ph, pl;
                    ph.x = h0; ph.y = h1; pl.x = l0; pl.y = l1;
                    *(__nv_bfloat162*)(g_h_hi + (size_t)slot * FFN_H + col) = ph;
                    *(__nv_bfloat162*)(g_h_lo + (size_t)slot * FFN_H + col) = pl;
                }
            }
        }
    }
}

// ============ grouped GEMM2: out[tok] += wt * (h[slot] @ w2[e]^T + b2[e]) ============
__global__ __launch_bounds__(256, 1) void gemm2_mma(const float* __restrict__ b2,
                                                    float* __restrict__ out) {
    const int e = blockIdx.z;
    const int cnt = g_cnt[e];
    const int row0 = blockIdx.y * BM;
    if (row0 >= cnt) return;
    const int col0 = blockIdx.x * BN;

    extern __shared__ char sm[];
    __shared__ int   toks[BM];
    __shared__ float wts[BM];
    __shared__ int   slots[BM];

    const int tid = threadIdx.x;
    if (tid < BM) {
        int r = row0 + tid;
        toks[tid]  = (r < cnt) ? g_tok[e * CAP + r]  : -1;
        slots[tid] = (r < cnt) ? g_slot[e * CAP + r] : 0;
        wts[tid]   = (r < cnt) ? g_wt[e * CAP + r]   : 0.f;
    }
    __syncthreads();

    const uint32_t smb = smem_u32(sm);
    const int lr = tid >> 1;
    const int lc0 = (tid & 1) * 4;

    const size_t a_row_off = (size_t)slots[lr] * FFN_H;
    const size_t b_row_off = ((size_t)e * D_MODEL + col0 + lr) * FFN_H;

    float acc[4][4][4];
#pragma unroll
    for (int mi = 0; mi < 4; mi++)
#pragma unroll
        for (int ni = 0; ni < 4; ni++)
#pragma unroll
            for (int q = 0; q < 4; q++) acc[mi][ni][q] = 0.f;

    const int lane = tid & 31;
    const int wid = tid >> 5;
    const int wm = wid >> 2;
    const int wn = wid & 3;
    const int arow = lane & 15, ahalf = lane >> 4;
    const int brow = lane & 7,  bhalf = (lane >> 3) & 1;

    const int NT = FFN_H / BKT;           // 32

    {
        const int k0 = 0;
        uint32_t st = smb;
#pragma unroll
        for (int j = 0; j < 4; j++) {
            uint32_t off = (uint32_t)lr * 128 + (lc0 + j) * 16;
            uint32_t so = swz(off);
            CP16(st + OFF_AH + so, (const void*)(g_h_hi + a_row_off + k0 + (lc0 + j) * 8));
            CP16(st + OFF_AL + so, (const void*)(g_h_lo + a_row_off + k0 + (lc0 + j) * 8));
            CP16(st + OFF_BH + so, (const void*)(g_w2_hi + b_row_off + k0 + (lc0 + j) * 8));
            CP16(st + OFF_BL + so, (const void*)(g_w2_lo + b_row_off + k0 + (lc0 + j) * 8));
        }
        CP_COMMIT();
    }

#pragma unroll 1
    for (int it = 0; it < NT; it++) {
        if (it + 1 < NT) {
            const int k0 = (it + 1) * BKT;
            uint32_t st = smb + ((it + 1) & 1) * STAGE_TOTAL;
#pragma unroll
            for (int j = 0; j < 4; j++) {
                uint32_t off = (uint32_t)lr * 128 + (lc0 + j) * 16;
                uint32_t so = swz(off);
                CP16(st + OFF_AH + so, (const void*)(g_h_hi + a_row_off + k0 + (lc0 + j) * 8));
                CP16(st + OFF_AL + so, (const void*)(g_h_lo + a_row_off + k0 + (lc0 + j) * 8));
                CP16(st + OFF_BH + so, (const void*)(g_w2_hi + b_row_off + k0 + (lc0 + j) * 8));
                CP16(st + OFF_BL + so, (const void*)(g_w2_lo + b_row_off + k0 + (lc0 + j) * 8));
            }
            CP_COMMIT();
            CP_WAIT1();
        } else {
            CP_WAIT0();
        }
        __syncthreads();

        const uint32_t sb = smb + (it & 1) * STAGE_TOTAL;
#pragma unroll
        for (int kk = 0; kk < 4; kk++) {
            uint32_t ah[4][4], al[4][4], bh[4][2], bl[4][2];
#pragma unroll
            for (int mi = 0; mi < 4; mi++) {
                uint32_t off = (uint32_t)(wm * 64 + mi * 16 + arow) * 128 + kk * 32 + ahalf * 16;
                uint32_t so = swz(off);
                LDSM4(ah[mi], sb + OFF_AH + so);
                LDSM4(al[mi], sb + OFF_AL + so);
            }
#pragma unroll
            for (int ni = 0; ni < 4; ni++) {
                uint32_t off = (uint32_t)(wn * 32 + ni * 8 + brow) * 128 + kk * 32 + bhalf * 16;
                uint32_t so = swz(off);
                LDSM2(bh[ni], sb + OFF_BH + so);
                LDSM2(bl[ni], sb + OFF_BL + so);
            }
#pragma unroll
            for (int mi = 0; mi < 4; mi++)
#pragma unroll
                for (int ni = 0; ni < 4; ni++) MMA16816(acc[mi][ni], ah[mi], bh[ni]);
#pragma unroll
            for (int mi = 0; mi < 4; mi++)
#pragma unroll
                for (int ni = 0; ni < 4; ni++) MMA16816(acc[mi][ni], ah[mi], bl[ni]);
#pragma unroll
            for (int mi = 0; mi < 4; mi++)
#pragma unroll
                for (int ni = 0; ni < 4; ni++) MMA16816(acc[mi][ni], al[mi], bh[ni]);
        }
        __syncthreads();
    }

    // ---- epilogue: weighted atomic scatter ----
    const int gr = lane >> 2, gc2 = (lane & 3) * 2;
    const float* b2e = b2 + (size_t)e * D_MODEL;
#pragma unroll
    for (int mi = 0; mi < 4; mi++) {
#pragma unroll
        for (int ni = 0; ni < 4; ni++) {
            int col = col0 + wn * 32 + ni * 8 + gc2;
            float bv0 = b2e[col], bv1 = b2e[col + 1];
#pragma unroll
            for (int half = 0; half < 2; half++) {
                int r = wm * 64 + mi * 16 + gr + half * 8;
                int tok = toks[r];
                if (tok >= 0) {
                    float wt = wts[r];
                    float v0 = (acc[mi][ni][half * 2 + 0] + bv0) * wt;
                    float v1 = (acc[mi][ni][half * 2 + 1] + bv1) * wt;
                    atomicAdd(out + (size_t)tok * D_MODEL + col,     v0);
                    atomicAdd(out + (size_t)tok * D_MODEL + col + 1, v1);
                }
            }
        }
    }
}

// ---------------- launch ----------------
extern "C" void kernel_launch(void* const* d_in, const int* in_sizes, int n_in,
                              void* d_out, int out_size) {
    const float* x  = (const float*)d_in[0];
    const float* rw = (const float*)d_in[1];
    const float* w1 = (const float*)d_in[2];
    const float* b1 = (const float*)d_in[3];
    const float* w2 = (const float*)d_in[4];
    const float* b2 = (const float*)d_in[5];
    float* out = (float*)d_out;

    cudaFuncSetAttribute(gemm1_mma, cudaFuncAttributeMaxDynamicSharedMemorySize, SMEM_DYN);
    cudaFuncSetAttribute(gemm2_mma, cudaFuncAttributeMaxDynamicSharedMemorySize, SMEM_DYN);

    const int n4 = N_TOK * D_MODEL / 4;
    zero_kernel<<<(n4 + 255) / 256, 256>>>((float4*)out, n4);

    __nv_bfloat162 *xh2, *xl2, *w1h2, *w1l2, *w2h2, *w2l2;
    cudaGetSymbolAddress((void**)&xh2, g_x_hi);   cudaGetSymbolAddress((void**)&xl2, g_x_lo);
    cudaGetSymbolAddress((void**)&w1h2, g_w1_hi); cudaGetSymbolAddress((void**)&w1l2, g_w1_lo);
    cudaGetSymbolAddress((void**)&w2h2, g_w2_hi); cudaGetSymbolAddress((void**)&w2l2, g_w2_lo);

    int nx4 = N_TOK * D_MODEL / 4;
    split_kernel<<<(nx4 + 255) / 256, 256>>>((const float4*)x, xh2, xl2, nx4);
    int nw4 = N_EXP * FFN_H * D_MODEL / 4;
    split_kernel<<<(nw4 + 255) / 256, 256>>>((const float4*)w1, w1h2, w1l2, nw4);
    split_kernel<<<(nw4 + 255) / 256, 256>>>((const float4*)w2, w2h2, w2l2, nw4);

    router_kernel<<<N_TOK, 256>>>(x, rw);
    psum_kernel<<<N_EXP, 256>>>();
    aux_kernel<<<1, 32>>>(out, out_size);

    dim3 g1(FFN_H / BN, N_TOK / BM, N_EXP);
    gemm1_mma<<<g1, 256, SMEM_DYN>>>(b1);
    dim3 g2(D_MODEL / BN, N_TOK / BM, N_EXP);
    gemm2_mma<<<g2, 256, SMEM_DYN>>>(b2, out);
}

// round 4
// speedup vs baseline: 2.5625x; 1.0202x over previous
#include <cuda_runtime.h>
#include <cuda_bf16.h>
#include <math.h>
#include <stdint.h>

#define D_MODEL 1024
#define N_EXP   8
#define N_TOK   4096
#define FFN_H   2048
#define CAP     N_TOK

// ---------------- device scratch ----------------
__device__ int   g_cnt[N_EXP];
__device__ int   g_tok[N_EXP * CAP];
__device__ int   g_slot[N_EXP * CAP];
__device__ float g_wt[N_EXP * CAP];
__device__ float g_probs[N_TOK * N_EXP];
__device__ float g_psum[N_EXP];

__device__ __align__(16) __nv_bfloat16 g_x_hi[(size_t)N_TOK * D_MODEL];
__device__ __align__(16) __nv_bfloat16 g_x_lo[(size_t)N_TOK * D_MODEL];
__device__ __align__(16) __nv_bfloat16 g_w1_hi[(size_t)N_EXP * FFN_H * D_MODEL];
__device__ __align__(16) __nv_bfloat16 g_w1_lo[(size_t)N_EXP * FFN_H * D_MODEL];
__device__ __align__(16) __nv_bfloat16 g_w2_hi[(size_t)N_EXP * D_MODEL * FFN_H];
__device__ __align__(16) __nv_bfloat16 g_w2_lo[(size_t)N_EXP * D_MODEL * FFN_H];
__device__ __align__(16) __nv_bfloat16 g_h_hi[(size_t)2 * N_TOK * FFN_H];
__device__ __align__(16) __nv_bfloat16 g_h_lo[(size_t)2 * N_TOK * FFN_H];

// ---------------- portable PTX helpers ----------------
__device__ __forceinline__ uint32_t smem_u32(const void* p) {
    uint32_t a;
    asm("{ .reg .u64 t; cvta.to.shared.u64 t, %1; cvt.u32.u64 %0, t; }" : "=r"(a) : "l"(p));
    return a;
}

#define CP16(dst, src) \
    asm volatile("cp.async.cg.shared.global [%0], [%1], 16;" :: "r"(dst), "l"(src))
#define CP_COMMIT() asm volatile("cp.async.commit_group;" ::: "memory")
#define CP_WAIT0()  asm volatile("cp.async.wait_group 0;" ::: "memory")
#define CP_WAIT1()  asm volatile("cp.async.wait_group 1;" ::: "memory")

#define LDSM4(r, addr) \
    asm volatile("ldmatrix.sync.aligned.m8n8.x4.shared.b16 {%0,%1,%2,%3}, [%4];" \
                 : "=r"((r)[0]), "=r"((r)[1]), "=r"((r)[2]), "=r"((r)[3]) : "r"(addr))

#define MMA16816(c, a, b) \
    asm volatile("mma.sync.aligned.m16n8k16.row.col.f32.bf16.bf16.f32 " \
                 "{%0,%1,%2,%3}, {%4,%5,%6,%7}, {%8,%9}, {%0,%1,%2,%3};" \
                 : "+f"((c)[0]), "+f"((c)[1]), "+f"((c)[2]), "+f"((c)[3]) \
                 : "r"((a)[0]), "r"((a)[1]), "r"((a)[2]), "r"((a)[3]), \
                   "r"((b)[0]), "r"((b)[1]))

__device__ __forceinline__ uint32_t swz(uint32_t off) { return off ^ ((off >> 3) & 0x70); }

// ---------------- tile geometry ----------------
#define BM 128
#define BN 128
#define BKT 64
#define OFF_AH 0
#define OFF_AL 16384
#define OFF_BH 32768
#define OFF_BL 49152
#define STAGE_TOTAL 65536
#define NSTAGE 3
#define SMEM_DYN (NSTAGE * STAGE_TOTAL)

// ---------------- init ----------------
__global__ void zero_kernel(float4* out4, int n4) {
    int i = blockIdx.x * blockDim.x + threadIdx.x;
    if (i < n4) out4[i] = make_float4(0.f, 0.f, 0.f, 0.f);
    if (i < N_EXP) g_cnt[i] = 0;
}

// ---------------- warp-per-token router ----------------
__global__ __launch_bounds__(256) void router_kernel(const float4* __restrict__ x4,
                                                     const float4* __restrict__ rw4) {
    const int lane = threadIdx.x & 31;
    const int wid = threadIdx.x >> 5;
    const int n = blockIdx.x * 8 + wid;
    if (n >= N_TOK) return;

    const float4* xr = x4 + (size_t)n * (D_MODEL / 4);
    float part[N_EXP];
#pragma unroll
    for (int e = 0; e < N_EXP; e++) part[e] = 0.f;
#pragma unroll
    for (int i = 0; i < 8; i++) {
        float4 v = xr[lane + 32 * i];
#pragma unroll
        for (int e = 0; e < N_EXP; e++) {
            float4 w = rw4[e * (D_MODEL / 4) + lane + 32 * i];
            part[e] += v.x * w.x + v.y * w.y + v.z * w.z + v.w * w.w;
        }
    }
#pragma unroll
    for (int o = 16; o > 0; o >>= 1) {
#pragma unroll
        for (int e = 0; e < N_EXP; e++)
            part[e] += __shfl_xor_sync(0xFFFFFFFF, part[e], o);
    }
    if (lane == 0) {
        float m = part[0];
#pragma unroll
        for (int e = 1; e < N_EXP; e++) m = fmaxf(m, part[e]);
        float p[N_EXP], s = 0.f;
#pragma unroll
        for (int e = 0; e < N_EXP; e++) { p[e] = expf(part[e] - m); s += p[e]; }
        float inv = 1.f / s;
#pragma unroll
        for (int e = 0; e < N_EXP; e++) { p[e] *= inv; g_probs[n * N_EXP + e] = p[e]; }
        int i1 = 0;
#pragma unroll
        for (int e = 1; e < N_EXP; e++) if (part[e] > part[i1]) i1 = e;
        int i2 = (i1 == 0) ? 1 : 0;
#pragma unroll
        for (int e = 0; e < N_EXP; e++) if (e != i1 && part[e] > part[i2]) i2 = e;
        float denom = p[i1] + p[i2];
        int pos1 = atomicAdd(&g_cnt[i1], 1);
        g_tok[i1 * CAP + pos1] = n; g_slot[i1 * CAP + pos1] = 2 * n; g_wt[i1 * CAP + pos1] = p[i1] / denom;
        int pos2 = atomicAdd(&g_cnt[i2], 1);
        g_tok[i2 * CAP + pos2] = n; g_slot[i2 * CAP + pos2] = 2 * n + 1; g_wt[i2 * CAP + pos2] = p[i2] / denom;
    }
}

__global__ __launch_bounds__(256) void psum_kernel() {
    const int e = blockIdx.x;
    const int tid = threadIdx.x;
    float s = 0.f;
    for (int n = tid; n < N_TOK; n += 256) s += g_probs[n * N_EXP + e];
    __shared__ float r[256];
    r[tid] = s;
    __syncthreads();
    for (int st = 128; st > 0; st >>= 1) {
        if (tid < st) r[tid] += r[tid + st];
        __syncthreads();
    }
    if (tid == 0) g_psum[e] = r[0];
}

__global__ void aux_kernel(float* out, int out_size) {
    if (threadIdx.x == 0 && blockIdx.x == 0) {
        float a = 0.f;
#pragma unroll
        for (int e = 0; e < N_EXP; e++) {
            float f = (float)g_cnt[e] / (float)(N_TOK * 2);
            float P = g_psum[e] / (float)N_TOK;
            a += f * P;
        }
        a *= (float)N_EXP;
        if (out_size > N_TOK * D_MODEL) out[N_TOK * D_MODEL] = a;
    }
}

// ---------------- fp32 -> bf16 hi/lo split ----------------
__global__ __launch_bounds__(256) void split_kernel(const float4* __restrict__ in,
                                                    __nv_bfloat162* __restrict__ hi2,
                                                    __nv_bfloat162* __restrict__ lo2, int n4) {
    int i = blockIdx.x * blockDim.x + threadIdx.x;
    if (i >= n4) return;
    float4 v = in[i];
    __nv_bfloat16 h0 = __float2bfloat16(v.x), h1 = __float2bfloat16(v.y);
    __nv_bfloat16 h2 = __float2bfloat16(v.z), h3 = __float2bfloat16(v.w);
    __nv_bfloat16 l0 = __float2bfloat16(v.x - __bfloat162float(h0));
    __nv_bfloat16 l1 = __float2bfloat16(v.y - __bfloat162float(h1));
    __nv_bfloat16 l2 = __float2bfloat16(v.z - __bfloat162float(h2));
    __nv_bfloat16 l3 = __float2bfloat16(v.w - __bfloat162float(h3));
    __nv_bfloat162 a, b, c, d;
    a.x = h0; a.y = h1; b.x = h2; b.y = h3;
    c.x = l0; c.y = l1; d.x = l2; d.y = l3;
    hi2[2 * i] = a; hi2[2 * i + 1] = b;
    lo2[2 * i] = c; lo2[2 * i + 1] = d;
}

// stage loader: each of 256 threads copies 4x16B per matrix
__device__ __forceinline__ void load_stage(uint32_t st, int lr, int lc0,
                                           const __nv_bfloat16* aH, const __nv_bfloat16* aL,
                                           const __nv_bfloat16* bH, const __nv_bfloat16* bL,
                                           int k0) {
#pragma unroll
    for (int j = 0; j < 4; j++) {
        uint32_t off = (uint32_t)lr * 128 + (lc0 + j) * 16;
        uint32_t so = swz(off);
        CP16(st + OFF_AH + so, (const void*)(aH + k0 + (lc0 + j) * 8));
        CP16(st + OFF_AL + so, (const void*)(aL + k0 + (lc0 + j) * 8));
        CP16(st + OFF_BH + so, (const void*)(bH + k0 + (lc0 + j) * 8));
        CP16(st + OFF_BL + so, (const void*)(bL + k0 + (lc0 + j) * 8));
    }
    CP_COMMIT();
}

// mainloop compute over one 64-wide K stage
__device__ __forceinline__ void compute_stage(uint32_t sb, float acc[4][4][4],
                                              int wm, int wn, int lane) {
    const int arow = lane & 15, ahalf = lane >> 4;
    const int nrow = ((lane >> 4) & 1) * 8 + (lane & 7);   // row within 16-row pair block
    const int bhalf = (lane >> 3) & 1;
#pragma unroll
    for (int kk = 0; kk < 4; kk++) {
        uint32_t ah[4][4], al[4][4], bh[2][4], bl[2][4];
#pragma unroll
        for (int mi = 0; mi < 4; mi++) {
            uint32_t off = (uint32_t)(wm * 64 + mi * 16 + arow) * 128 + kk * 32 + ahalf * 16;
            uint32_t so = swz(off);
            LDSM4(ah[mi], sb + OFF_AH + so);
            LDSM4(al[mi], sb + OFF_AL + so);
        }
#pragma unroll
        for (int p = 0; p < 2; p++) {
            uint32_t off = (uint32_t)(wn * 32 + p * 16 + nrow) * 128 + kk * 32 + bhalf * 16;
            uint32_t so = swz(off);
            LDSM4(bh[p], sb + OFF_BH + so);
            LDSM4(bl[p], sb + OFF_BL + so);
        }
#pragma unroll
        for (int mi = 0; mi < 4; mi++)
#pragma unroll
            for (int p = 0; p < 2; p++) {
                MMA16816(acc[mi][2 * p],     ah[mi], &bh[p][0]);
                MMA16816(acc[mi][2 * p + 1], ah[mi], &bh[p][2]);
            }
#pragma unroll
        for (int mi = 0; mi < 4; mi++)
#pragma unroll
            for (int p = 0; p < 2; p++) {
                MMA16816(acc[mi][2 * p],     ah[mi], &bl[p][0]);
                MMA16816(acc[mi][2 * p + 1], ah[mi], &bl[p][2]);
            }
#pragma unroll
        for (int mi = 0; mi < 4; mi++)
#pragma unroll
            for (int p = 0; p < 2; p++) {
                MMA16816(acc[mi][2 * p],     al[mi], &bh[p][0]);
                MMA16816(acc[mi][2 * p + 1], al[mi], &bh[p][2]);
            }
    }
}

// ============ grouped GEMM1 ============
__global__ __launch_bounds__(256, 1) void gemm1_mma(const float* __restrict__ b1) {
    const int e = blockIdx.z;
    const int cnt = g_cnt[e];
    const int row0 = blockIdx.y * BM;
    if (row0 >= cnt) return;
    const int col0 = blockIdx.x * BN;

    extern __shared__ char sm[];
    __shared__ int toks[BM];
    __shared__ int slots[BM];

    const int tid = threadIdx.x;
    if (tid < BM) {
        int r = row0 + tid;
        toks[tid]  = (r < cnt) ? g_tok[e * CAP + r]  : 0;
        slots[tid] = (r < cnt) ? g_slot[e * CAP + r] : -1;
    }
    __syncthreads();

    const uint32_t smb = smem_u32(sm);
    const int lr = tid >> 1;
    const int lc0 = (tid & 1) * 4;

    const __nv_bfloat16* aH = g_x_hi + (size_t)toks[lr] * D_MODEL;
    const __nv_bfloat16* aL = g_x_lo + (size_t)toks[lr] * D_MODEL;
    const __nv_bfloat16* bH = g_w1_hi + ((size_t)e * FFN_H + col0 + lr) * D_MODEL;
    const __nv_bfloat16* bL = g_w1_lo + ((size_t)e * FFN_H + col0 + lr) * D_MODEL;

    float acc[4][4][4];
#pragma unroll
    for (int mi = 0; mi < 4; mi++)
#pragma unroll
        for (int ni = 0; ni < 4; ni++)
#pragma unroll
            for (int q = 0; q < 4; q++) acc[mi][ni][q] = 0.f;

    const int lane = tid & 31;
    const int wid = tid >> 5;
    const int wm = wid >> 2, wn = wid & 3;
    const int NT = D_MODEL / BKT;   // 16

    load_stage(smb + 0 * STAGE_TOTAL, lr, lc0, aH, aL, bH, bL, 0);
    load_stage(smb + 1 * STAGE_TOTAL, lr, lc0, aH, aL, bH, bL, BKT);

#pragma unroll 1
    for (int it = 0; it < NT; it++) {
        if (it < NT - 1) { CP_WAIT1(); } else { CP_WAIT0(); }
        __syncthreads();
        if (it + 2 < NT)
            load_stage(smb + ((it + 2) % NSTAGE) * STAGE_TOTAL, lr, lc0, aH, aL, bH, bL, (it + 2) * BKT);
        compute_stage(smb + (it % NSTAGE) * STAGE_TOTAL, acc, wm, wn, lane);
    }

    // epilogue: bias + silu + hi/lo split store
    const int gr = lane >> 2, gc2 = (lane & 3) * 2;
    const float* b1e = b1 + (size_t)e * FFN_H;
#pragma unroll
    for (int mi = 0; mi < 4; mi++) {
#pragma unroll
        for (int ni = 0; ni < 4; ni++) {
            int col = col0 + wn * 32 + ni * 8 + gc2;
            float bv0 = b1e[col], bv1 = b1e[col + 1];
#pragma unroll
            for (int half = 0; half < 2; half++) {
                int r = wm * 64 + mi * 16 + gr + half * 8;
                int slot = slots[r];
                if (slot >= 0) {
                    float v0 = acc[mi][ni][half * 2 + 0] + bv0;
                    float v1 = acc[mi][ni][half * 2 + 1] + bv1;
                    float s0 = v0 / (1.f + expf(-v0));
                    float s1 = v1 / (1.f + expf(-v1));
                    __nv_bfloat16 h0 = __float2bfloat16(s0), h1 = __float2bfloat16(s1);
                    __nv_bfloat16 l0 = __float2bfloat16(s0 - __bfloat162float(h0));
                    __nv_bfloat16 l1 = __float2bfloat16(s1 - __bfloat162float(h1));
                    __nv_bfloat162 ph, pl;
                    ph.x = h0; ph.y = h1; pl.x = l0; pl.y = l1;
                    *(__nv_bfloat162*)(g_h_hi + (size_t)slot * FFN_H + col) = ph;
                    *(__nv_bfloat162*)(g_h_lo + (size_t)slot * FFN_H + col) = pl;
                }
            }
        }
    }
}

// ============ grouped GEMM2 ============
__global__ __launch_bounds__(256, 1) void gemm2_mma(const float* __restrict__ b2,
                                                    float* __restrict__ out) {
    const int e = blockIdx.z;
    const int cnt = g_cnt[e];
    const int row0 = blockIdx.y * BM;
    if (row0 >= cnt) return;
    const int col0 = blockIdx.x * BN;

    extern __shared__ char sm[];
    __shared__ int   toks[BM];
    __shared__ float wts[BM];
    __shared__ int   slots[BM];

    const int tid = threadIdx.x;
    if (tid < BM) {
        int r = row0 + tid;
        toks[tid]  = (r < cnt) ? g_tok[e * CAP + r]  : -1;
        slots[tid] = (r < cnt) ? g_slot[e * CAP + r] : 0;
        wts[tid]   = (r < cnt) ? g_wt[e * CAP + r]   : 0.f;
    }
    __syncthreads();

    const uint32_t smb = smem_u32(sm);
    const int lr = tid >> 1;
    const int lc0 = (tid & 1) * 4;

    const __nv_bfloat16* aH = g_h_hi + (size_t)slots[lr] * FFN_H;
    const __nv_bfloat16* aL = g_h_lo + (size_t)slots[lr] * FFN_H;
    const __nv_bfloat16* bH = g_w2_hi + ((size_t)e * D_MODEL + col0 + lr) * FFN_H;
    const __nv_bfloat16* bL = g_w2_lo + ((size_t)e * D_MODEL + col0 + lr) * FFN_H;

    float acc[4][4][4];
#pragma unroll
    for (int mi = 0; mi < 4; mi++)
#pragma unroll
        for (int ni = 0; ni < 4; ni++)
#pragma unroll
            for (int q = 0; q < 4; q++) acc[mi][ni][q] = 0.f;

    const int lane = tid & 31;
    const int wid = tid >> 5;
    const int wm = wid >> 2, wn = wid & 3;
    const int NT = FFN_H / BKT;   // 32

    load_stage(smb + 0 * STAGE_TOTAL, lr, lc0, aH, aL, bH, bL, 0);
    load_stage(smb + 1 * STAGE_TOTAL, lr, lc0, aH, aL, bH, bL, BKT);

#pragma unroll 1
    for (int it = 0; it < NT; it++) {
        if (it < NT - 1) { CP_WAIT1(); } else { CP_WAIT0(); }
        __syncthreads();
        if (it + 2 < NT)
            load_stage(smb + ((it + 2) % NSTAGE) * STAGE_TOTAL, lr, lc0, aH, aL, bH, bL, (it + 2) * BKT);
        compute_stage(smb + (it % NSTAGE) * STAGE_TOTAL, acc, wm, wn, lane);
    }

    // epilogue: weighted atomic scatter
    const int gr = lane >> 2, gc2 = (lane & 3) * 2;
    const float* b2e = b2 + (size_t)e * D_MODEL;
#pragma unroll
    for (int mi = 0; mi < 4; mi++) {
#pragma unroll
        for (int ni = 0; ni < 4; ni++) {
            int col = col0 + wn * 32 + ni * 8 + gc2;
            float bv0 = b2e[col], bv1 = b2e[col + 1];
#pragma unroll
            for (int half = 0; half < 2; half++) {
                int r = wm * 64 + mi * 16 + gr + half * 8;
                int tok = toks[r];
                if (tok >= 0) {
                    float wt = wts[r];
                    float v0 = (acc[mi][ni][half * 2 + 0] + bv0) * wt;
                    float v1 = (acc[mi][ni][half * 2 + 1] + bv1) * wt;
                    atomicAdd(out + (size_t)tok * D_MODEL + col,     v0);
                    atomicAdd(out + (size_t)tok * D_MODEL + col + 1, v1);
                }
            }
        }
    }
}

// ---------------- launch ----------------
extern "C" void kernel_launch(void* const* d_in, const int* in_sizes, int n_in,
                              void* d_out, int out_size) {
    const float* x  = (const float*)d_in[0];
    const float* rw = (const float*)d_in[1];
    const float* w1 = (const float*)d_in[2];
    const float* b1 = (const float*)d_in[3];
    const float* w2 = (const float*)d_in[4];
    const float* b2 = (const float*)d_in[5];
    float* out = (float*)d_out;

    cudaFuncSetAttribute(gemm1_mma, cudaFuncAttributeMaxDynamicSharedMemorySize, SMEM_DYN);
    cudaFuncSetAttribute(gemm2_mma, cudaFuncAttributeMaxDynamicSharedMemorySize, SMEM_DYN);

    const int n4 = N_TOK * D_MODEL / 4;
    zero_kernel<<<(n4 + 255) / 256, 256>>>((float4*)out, n4);

    __nv_bfloat162 *xh2, *xl2, *w1h2, *w1l2, *w2h2, *w2l2;
    cudaGetSymbolAddress((void**)&xh2, g_x_hi);   cudaGetSymbolAddress((void**)&xl2, g_x_lo);
    cudaGetSymbolAddress((void**)&w1h2, g_w1_hi); cudaGetSymbolAddress((void**)&w1l2, g_w1_lo);
    cudaGetSymbolAddress((void**)&w2h2, g_w2_hi); cudaGetSymbolAddress((void**)&w2l2, g_w2_lo);

    int nx4 = N_TOK * D_MODEL / 4;
    split_kernel<<<(nx4 + 255) / 256, 256>>>((const float4*)x, xh2, xl2, nx4);
    int nw4 = N_EXP * FFN_H * D_MODEL / 4;
    split_kernel<<<(nw4 + 255) / 256, 256>>>((const float4*)w1, w1h2, w1l2, nw4);
    split_kernel<<<(nw4 + 255) / 256, 256>>>((const float4*)w2, w2h2, w2l2, nw4);

    router_kernel<<<N_TOK / 8, 256>>>((const float4*)x, (const float4*)rw);
    psum_kernel<<<N_EXP, 256>>>();
    aux_kernel<<<1, 32>>>(out, out_size);

    dim3 g1(FFN_H / BN, N_TOK / BM, N_EXP);
    gemm1_mma<<<g1, 256, SMEM_DYN>>>(b1);
    dim3 g2(D_MODEL / BN, N_TOK / BM, N_EXP);
    gemm2_mma<<<g2, 256, SMEM_DYN>>>(b2, out);
}

// round 5
// speedup vs baseline: 5.8030x; 2.2646x over previous
#include <cuda_runtime.h>
#include <cuda_fp16.h>
#include <math.h>
#include <stdint.h>

#define D_MODEL 1024
#define N_EXP   8
#define N_TOK   4096
#define FFN_H   2048
#define CAP     N_TOK

// ---------------- device scratch ----------------
__device__ int   g_cnt[N_EXP];
__device__ int   g_tok[N_EXP * CAP];
__device__ int   g_slot[N_EXP * CAP];
__device__ float g_wt[N_EXP * CAP];
__device__ float g_probs[N_TOK * N_EXP];
__device__ float g_psum[N_EXP];

__device__ __align__(16) __half g_x_f16[(size_t)N_TOK * D_MODEL];
__device__ __align__(16) __half g_w1_f16[(size_t)N_EXP * FFN_H * D_MODEL];
__device__ __align__(16) __half g_w2_f16[(size_t)N_EXP * D_MODEL * FFN_H];
__device__ __align__(16) __half g_h_f16[(size_t)2 * N_TOK * FFN_H];

// ---------------- portable PTX helpers ----------------
__device__ __forceinline__ uint32_t smem_u32(const void* p) {
    uint32_t a;
    asm("{ .reg .u64 t; cvta.to.shared.u64 t, %1; cvt.u32.u64 %0, t; }" : "=r"(a) : "l"(p));
    return a;
}

#define CP16(dst, src) \
    asm volatile("cp.async.cg.shared.global [%0], [%1], 16;" :: "r"(dst), "l"(src))
#define CP_COMMIT() asm volatile("cp.async.commit_group;" ::: "memory")
#define CP_WAIT0()  asm volatile("cp.async.wait_group 0;" ::: "memory")

#define LDSM4(r, addr) \
    asm volatile("ldmatrix.sync.aligned.m8n8.x4.shared.b16 {%0,%1,%2,%3}, [%4];" \
                 : "=r"((r)[0]), "=r"((r)[1]), "=r"((r)[2]), "=r"((r)[3]) : "r"(addr))

#define MMA16816(c, a, b0, b1) \
    asm volatile("mma.sync.aligned.m16n8k16.row.col.f32.f16.f16.f32 " \
                 "{%0,%1,%2,%3}, {%4,%5,%6,%7}, {%8,%9}, {%0,%1,%2,%3};" \
                 : "+f"((c)[0]), "+f"((c)[1]), "+f"((c)[2]), "+f"((c)[3]) \
                 : "r"((a)[0]), "r"((a)[1]), "r"((a)[2]), "r"((a)[3]), \
                   "r"(b0), "r"(b1))

__device__ __forceinline__ uint32_t swz(uint32_t off) { return off ^ ((off >> 3) & 0x70); }

// ---------------- tile geometry ----------------
#define BM 128
#define BN 128
#define BKT 64
#define OFF_A 0
#define OFF_B 16384
#define STAGE_TOTAL 32768
#define SMEM_DYN (2 * STAGE_TOTAL)

// ---------------- init ----------------
__global__ void zero_kernel(float4* out4, int n4) {
    int i = blockIdx.x * blockDim.x + threadIdx.x;
    if (i < n4) out4[i] = make_float4(0.f, 0.f, 0.f, 0.f);
    if (i < N_EXP) g_cnt[i] = 0;
}

// ---------------- warp-per-token router ----------------
__global__ __launch_bounds__(256) void router_kernel(const float4* __restrict__ x4,
                                                     const float4* __restrict__ rw4) {
    const int lane = threadIdx.x & 31;
    const int wid = threadIdx.x >> 5;
    const int n = blockIdx.x * 8 + wid;
    if (n >= N_TOK) return;

    const float4* xr = x4 + (size_t)n * (D_MODEL / 4);
    float part[N_EXP];
#pragma unroll
    for (int e = 0; e < N_EXP; e++) part[e] = 0.f;
#pragma unroll
    for (int i = 0; i < 8; i++) {
        float4 v = xr[lane + 32 * i];
#pragma unroll
        for (int e = 0; e < N_EXP; e++) {
            float4 w = rw4[e * (D_MODEL / 4) + lane + 32 * i];
            part[e] += v.x * w.x + v.y * w.y + v.z * w.z + v.w * w.w;
        }
    }
#pragma unroll
    for (int o = 16; o > 0; o >>= 1) {
#pragma unroll
        for (int e = 0; e < N_EXP; e++)
            part[e] += __shfl_xor_sync(0xFFFFFFFF, part[e], o);
    }
    if (lane == 0) {
        float m = part[0];
#pragma unroll
        for (int e = 1; e < N_EXP; e++) m = fmaxf(m, part[e]);
        float p[N_EXP], s = 0.f;
#pragma unroll
        for (int e = 0; e < N_EXP; e++) { p[e] = expf(part[e] - m); s += p[e]; }
        float inv = 1.f / s;
#pragma unroll
        for (int e = 0; e < N_EXP; e++) { p[e] *= inv; g_probs[n * N_EXP + e] = p[e]; }
        int i1 = 0;
#pragma unroll
        for (int e = 1; e < N_EXP; e++) if (part[e] > part[i1]) i1 = e;
        int i2 = (i1 == 0) ? 1 : 0;
#pragma unroll
        for (int e = 0; e < N_EXP; e++) if (e != i1 && part[e] > part[i2]) i2 = e;
        float denom = p[i1] + p[i2];
        int pos1 = atomicAdd(&g_cnt[i1], 1);
        g_tok[i1 * CAP + pos1] = n; g_slot[i1 * CAP + pos1] = 2 * n; g_wt[i1 * CAP + pos1] = p[i1] / denom;
        int pos2 = atomicAdd(&g_cnt[i2], 1);
        g_tok[i2 * CAP + pos2] = n; g_slot[i2 * CAP + pos2] = 2 * n + 1; g_wt[i2 * CAP + pos2] = p[i2] / denom;
    }
}

__global__ __launch_bounds__(256) void psum_kernel() {
    const int e = blockIdx.x;
    const int tid = threadIdx.x;
    float s = 0.f;
    for (int n = tid; n < N_TOK; n += 256) s += g_probs[n * N_EXP + e];
    __shared__ float r[256];
    r[tid] = s;
    __syncthreads();
    for (int st = 128; st > 0; st >>= 1) {
        if (tid < st) r[tid] += r[tid + st];
        __syncthreads();
    }
    if (tid == 0) g_psum[e] = r[0];
}

__global__ void aux_kernel(float* out, int out_size) {
    if (threadIdx.x == 0 && blockIdx.x == 0) {
        float a = 0.f;
#pragma unroll
        for (int e = 0; e < N_EXP; e++) {
            float f = (float)g_cnt[e] / (float)(N_TOK * 2);
            float P = g_psum[e] / (float)N_TOK;
            a += f * P;
        }
        a *= (float)N_EXP;
        if (out_size > N_TOK * D_MODEL) out[N_TOK * D_MODEL] = a;
    }
}

// ---------------- fp32 -> fp16 convert ----------------
__global__ __launch_bounds__(256) void cvt_kernel(const float4* __restrict__ in,
                                                  __half2* __restrict__ o2, int n4) {
    int i = blockIdx.x * blockDim.x + threadIdx.x;
    if (i >= n4) return;
    float4 v = in[i];
    o2[2 * i]     = __floats2half2_rn(v.x, v.y);
    o2[2 * i + 1] = __floats2half2_rn(v.z, v.w);
}

// stage loader: 256 threads, A 16KB (4 chunks/thr) + B 16KB (4 chunks/thr)
__device__ __forceinline__ void load_stage(uint32_t st, int lr, int lc0,
                                           const __half* a, const __half* b, int k0) {
#pragma unroll
    for (int j = 0; j < 4; j++) {
        uint32_t off = (uint32_t)lr * 128 + (lc0 + j) * 16;
        uint32_t so = swz(off);
        CP16(st + OFF_A + so, (const void*)(a + k0 + (lc0 + j) * 8));
        CP16(st + OFF_B + so, (const void*)(b + k0 + (lc0 + j) * 8));
    }
    CP_COMMIT();
}

// compute one 64-wide K stage; warp tile 64x32
__device__ __forceinline__ void compute_stage(uint32_t sb, float acc[4][4][4],
                                              int wm, int wn, int lane) {
    const int arow = lane & 15, ahalf = lane >> 4;
    const int nrow = ((lane >> 4) & 1) * 8 + (lane & 7);
    const int bhalf = (lane >> 3) & 1;
#pragma unroll
    for (int kk = 0; kk < 4; kk++) {
        uint32_t ah[4][4], bf[2][4];
#pragma unroll
        for (int mi = 0; mi < 4; mi++) {
            uint32_t off = (uint32_t)(wm * 64 + mi * 16 + arow) * 128 + kk * 32 + ahalf * 16;
            LDSM4(ah[mi], sb + OFF_A + swz(off));
        }
#pragma unroll
        for (int p = 0; p < 2; p++) {
            uint32_t off = (uint32_t)(wn * 32 + p * 16 + nrow) * 128 + kk * 32 + bhalf * 16;
            LDSM4(bf[p], sb + OFF_B + swz(off));
        }
#pragma unroll
        for (int mi = 0; mi < 4; mi++) {
#pragma unroll
            for (int p = 0; p < 2; p++) {
                MMA16816(acc[mi][2 * p],     ah[mi], bf[p][0], bf[p][1]);
                MMA16816(acc[mi][2 * p + 1], ah[mi], bf[p][2], bf[p][3]);
            }
        }
    }
}

// ============ grouped GEMM1: h[slot] = silu(x[tok] @ w1[e]^T + b1[e]) ============
__global__ __launch_bounds__(256, 2) void gemm1_mma(const float* __restrict__ b1) {
    const int e = blockIdx.z;
    const int cnt = g_cnt[e];
    const int row0 = blockIdx.y * BM;
    if (row0 >= cnt) return;
    const int col0 = blockIdx.x * BN;

    extern __shared__ char sm[];
    __shared__ int toks[BM];
    __shared__ int slots[BM];

    const int tid = threadIdx.x;
    if (tid < BM) {
        int r = row0 + tid;
        toks[tid]  = (r < cnt) ? g_tok[e * CAP + r]  : 0;
        slots[tid] = (r < cnt) ? g_slot[e * CAP + r] : -1;
    }
    __syncthreads();

    const uint32_t smb = smem_u32(sm);
    const int lr = tid >> 1;
    const int lc0 = (tid & 1) * 4;

    const __half* aP = g_x_f16 + (size_t)toks[lr] * D_MODEL;
    const __half* bP = g_w1_f16 + ((size_t)e * FFN_H + col0 + lr) * D_MODEL;

    float acc[4][4][4];
#pragma unroll
    for (int mi = 0; mi < 4; mi++)
#pragma unroll
        for (int ni = 0; ni < 4; ni++)
#pragma unroll
            for (int q = 0; q < 4; q++) acc[mi][ni][q] = 0.f;

    const int lane = tid & 31;
    const int wid = tid >> 5;
    const int wm = wid >> 2, wn = wid & 3;
    const int NT = D_MODEL / BKT;   // 16

    load_stage(smb, lr, lc0, aP, bP, 0);

#pragma unroll 1
    for (int it = 0; it < NT; it++) {
        CP_WAIT0();
        __syncthreads();
        if (it + 1 < NT)
            load_stage(smb + ((it + 1) & 1) * STAGE_TOTAL, lr, lc0, aP, bP, (it + 1) * BKT);
        compute_stage(smb + (it & 1) * STAGE_TOTAL, acc, wm, wn, lane);
        __syncthreads();
    }

    // epilogue: bias + silu + fp16 store
    const int gr = lane >> 2, gc2 = (lane & 3) * 2;
    const float* b1e = b1 + (size_t)e * FFN_H;
#pragma unroll
    for (int mi = 0; mi < 4; mi++) {
#pragma unroll
        for (int ni = 0; ni < 4; ni++) {
            int col = col0 + wn * 32 + ni * 8 + gc2;
            float bv0 = b1e[col], bv1 = b1e[col + 1];
#pragma unroll
            for (int half = 0; half < 2; half++) {
                int r = wm * 64 + mi * 16 + gr + half * 8;
                int slot = slots[r];
                if (slot >= 0) {
                    float v0 = acc[mi][ni][half * 2 + 0] + bv0;
                    float v1 = acc[mi][ni][half * 2 + 1] + bv1;
                    float s0 = v0 / (1.f + expf(-v0));
                    float s1 = v1 / (1.f + expf(-v1));
                    *(__half2*)(g_h_f16 + (size_t)slot * FFN_H + col) = __floats2half2_rn(s0, s1);
                }
            }
        }
    }
}

// ============ grouped GEMM2: out[tok] += wt * (h[slot] @ w2[e]^T + b2[e]) ============
__global__ __launch_bounds__(256, 2) void gemm2_mma(const float* __restrict__ b2,
                                                    float* __restrict__ out) {
    const int e = blockIdx.z;
    const int cnt = g_cnt[e];
    const int row0 = blockIdx.y * BM;
    if (row0 >= cnt) return;
    const int col0 = blockIdx.x * BN;

    extern __shared__ char sm[];
    __shared__ int   toks[BM];
    __shared__ float wts[BM];
    __shared__ int   slots[BM];

    const int tid = threadIdx.x;
    if (tid < BM) {
        int r = row0 + tid;
        toks[tid]  = (r < cnt) ? g_tok[e * CAP + r]  : -1;
        slots[tid] = (r < cnt) ? g_slot[e * CAP + r] : 0;
        wts[tid]   = (r < cnt) ? g_wt[e * CAP + r]   : 0.f;
    }
    __syncthreads();

    const uint32_t smb = smem_u32(sm);
    const int lr = tid >> 1;
    const int lc0 = (tid & 1) * 4;

    const __half* aP = g_h_f16 + (size_t)slots[lr] * FFN_H;
    const __half* bP = g_w2_f16 + ((size_t)e * D_MODEL + col0 + lr) * FFN_H;

    float acc[4][4][4];
#pragma unroll
    for (int mi = 0; mi < 4; mi++)
#pragma unroll
        for (int ni = 0; ni < 4; ni++)
#pragma unroll
            for (int q = 0; q < 4; q++) acc[mi][ni][q] = 0.f;

    const int lane = tid & 31;
    const int wid = tid >> 5;
    const int wm = wid >> 2, wn = wid & 3;
    const int NT = FFN_H / BKT;   // 32

    load_stage(smb, lr, lc0, aP, bP, 0);

#pragma unroll 1
    for (int it = 0; it < NT; it++) {
        CP_WAIT0();
        __syncthreads();
        if (it + 1 < NT)
            load_stage(smb + ((it + 1) & 1) * STAGE_TOTAL, lr, lc0, aP, bP, (it + 1) * BKT);
        compute_stage(smb + (it & 1) * STAGE_TOTAL, acc, wm, wn, lane);
        __syncthreads();
    }

    // epilogue: weighted atomic scatter
    const int gr = lane >> 2, gc2 = (lane & 3) * 2;
    const float* b2e = b2 + (size_t)e * D_MODEL;
#pragma unroll
    for (int mi = 0; mi < 4; mi++) {
#pragma unroll
        for (int ni = 0; ni < 4; ni++) {
            int col = col0 + wn * 32 + ni * 8 + gc2;
            float bv0 = b2e[col], bv1 = b2e[col + 1];
#pragma unroll
            for (int half = 0; half < 2; half++) {
                int r = wm * 64 + mi * 16 + gr + half * 8;
                int tok = toks[r];
                if (tok >= 0) {
                    float wt = wts[r];
                    float v0 = (acc[mi][ni][half * 2 + 0] + bv0) * wt;
                    float v1 = (acc[mi][ni][half * 2 + 1] + bv1) * wt;
                    atomicAdd(out + (size_t)tok * D_MODEL + col,     v0);
                    atomicAdd(out + (size_t)tok * D_MODEL + col + 1, v1);
                }
            }
        }
    }
}

// ---------------- launch ----------------
extern "C" void kernel_launch(void* const* d_in, const int* in_sizes, int n_in,
                              void* d_out, int out_size) {
    const float* x  = (const float*)d_in[0];
    const float* rw = (const float*)d_in[1];
    const float* w1 = (const float*)d_in[2];
    const float* b1 = (const float*)d_in[3];
    const float* w2 = (const float*)d_in[4];
    const float* b2 = (const float*)d_in[5];
    float* out = (float*)d_out;

    cudaFuncSetAttribute(gemm1_mma, cudaFuncAttributeMaxDynamicSharedMemorySize, SMEM_DYN);
    cudaFuncSetAttribute(gemm2_mma, cudaFuncAttributeMaxDynamicSharedMemorySize, SMEM_DYN);

    const int n4 = N_TOK * D_MODEL / 4;
    zero_kernel<<<(n4 + 255) / 256, 256>>>((float4*)out, n4);

    __half2 *xh, *w1h, *w2h;
    cudaGetSymbolAddress((void**)&xh, g_x_f16);
    cudaGetSymbolAddress((void**)&w1h, g_w1_f16);
    cudaGetSymbolAddress((void**)&w2h, g_w2_f16);

    int nx4 = N_TOK * D_MODEL / 4;
    cvt_kernel<<<(nx4 + 255) / 256, 256>>>((const float4*)x, xh, nx4);
    int nw4 = N_EXP * FFN_H * D_MODEL / 4;
    cvt_kernel<<<(nw4 + 255) / 256, 256>>>((const float4*)w1, w1h, nw4);
    cvt_kernel<<<(nw4 + 255) / 256, 256>>>((const float4*)w2, w2h, nw4);

    router_kernel<<<N_TOK / 8, 256>>>((const float4*)x, (const float4*)rw);
    psum_kernel<<<N_EXP, 256>>>();
    aux_kernel<<<1, 32>>>(out, out_size);

    dim3 g1(FFN_H / BN, N_TOK / BM, N_EXP);
    gemm1_mma<<<g1, 256, SMEM_DYN>>>(b1);
    dim3 g2(D_MODEL / BN, N_TOK / BM, N_EXP);
    gemm2_mma<<<g2, 256, SMEM_DYN>>>(b2, out);
}